// round 1
// baseline (speedup 1.0000x reference)
#include <cuda_runtime.h>
#include <math.h>

// yolo_v3 head: out[b, cell, c] = f(x[b, c, cell])
//   b in [0,32), cell in [0,4096), c = a*85 + d, a in [0,3), d in [0,85)
//   S = 64, stride = 512/64 = 8
// f:
//   d==0: (sigmoid(v) + (cell % 64)) * 8
//   d==1: (sigmoid(v) + (cell / 64)) * 8
//   d==2: exp(v) * anchors[a*2+0]      // (anchors/8)*8 exact in fp32
//   d==3: exp(v) * anchors[a*2+1]
//   else: sigmoid(v)

#define S_GRID 64
#define WH 4096
#define NDIM 85
#define NANC 3
#define NCHAN 255     // NANC * NDIM
#define FSTRIDE 8.0f

__device__ __forceinline__ float fast_sigmoid(float v) {
    return __fdividef(1.0f, 1.0f + __expf(-v));
}

__global__ void __launch_bounds__(256) yolo_head_kernel(
    const float* __restrict__ x,        // [B, 255, 4096]
    const float* __restrict__ anchors,  // [3, 2]
    float* __restrict__ out)            // [B, 4096, 255]
{
    __shared__ float tile[32][33];      // +1 pad: conflict-free transposed reads

    const int b     = blockIdx.z;
    const int cell0 = blockIdx.x * 32;  // 128 cell tiles
    const int chan0 = blockIdx.y * 32;  // 8 channel tiles (last partial: 31 chans)

    const float* xb = x   + (size_t)b * NCHAN * WH;
    float*       ob = out + (size_t)b * WH * NCHAN;

    const int tx = threadIdx.x;         // 0..31
    const int ty = threadIdx.y;         // 0..7

    // Load: coalesced along cells (input rows are cell-contiguous)
    #pragma unroll
    for (int j = 0; j < 32; j += 8) {
        const int c = chan0 + ty + j;
        if (c < NCHAN)
            tile[ty + j][tx] = xb[(size_t)c * WH + (cell0 + tx)];
    }
    __syncthreads();

    // Store: coalesced along channels (output rows are channel-contiguous)
    #pragma unroll
    for (int j = 0; j < 32; j += 8) {
        const int cell = cell0 + ty + j;
        const int c    = chan0 + tx;
        if (c < NCHAN) {
            const float v = tile[tx][ty + j];
            const int a = c / NDIM;        // 0..2
            const int d = c - a * NDIM;    // 0..84
            float r;
            if (d >= 4) {
                r = fast_sigmoid(v);
            } else if (d == 0) {
                r = (fast_sigmoid(v) + (float)(cell & (S_GRID - 1))) * FSTRIDE;
            } else if (d == 1) {
                r = (fast_sigmoid(v) + (float)(cell >> 6)) * FSTRIDE;
            } else { // d == 2 or 3
                r = __expf(v) * __ldg(&anchors[a * 2 + (d - 2)]);
            }
            ob[(size_t)cell * NCHAN + c] = r;
        }
    }
}

extern "C" void kernel_launch(void* const* d_in, const int* in_sizes, int n_in,
                              void* d_out, int out_size) {
    const float* x       = (const float*)d_in[0];   // [32, 255, 64, 64] fp32
    const float* anchors = (const float*)d_in[1];   // [3, 2] fp32
    float* out           = (float*)d_out;           // [32, 12288, 85] fp32

    dim3 block(32, 8, 1);
    dim3 grid(WH / 32, (NCHAN + 31) / 32, 32);      // (128, 8, 32)
    yolo_head_kernel<<<grid, block>>>(x, anchors, out);
}